// round 17
// baseline (speedup 1.0000x reference)
#include <cuda_runtime.h>

// SoftDTW-variant, gamma=1, B=32, T=512, row-broadcast cost ds[i]=(x[i]-y[i])^2.
// Linear-weight domain: W(i,j) = 2^(P(i) - R(i,j)*log2e), P(i)=sum_{r<=i} ds'[r].
//   W(i,j) = W(i-1,j) + W(i-1,j-1) + c_i * W(i,j-1),  c_i = 2^(-ds'[i]) <= 1
// Guard-free commits, raw u, joint pre-tile renorm (R13-proven numerics).
//
// R17: ONE WARP PER BATCH, 16 columns/lane -> the seam (smem ring, spin,
// release/acquire, inter-warp skew) is gone. 95 wall slots, handoff is pure
// shfl. 8 rows/superstep; per-slot 256 fma-pipe instrs ~ 512 cy, chain and
// issue balanced; alu-side renorm rides in fma gaps.

#define TLEN  512
#define BATCH 32
#define NTH   32
#define ROWS  8
#define CPL   16                  // columns per lane
#define RB    (TLEN / ROWS)       // 64 row-blocks
#define WSUP  (RB + 31)           // 95 supersteps

__global__ __launch_bounds__(NTH, 1) void softdtw_kernel(const float* __restrict__ x,
                                                         const float* __restrict__ y,
                                                         float* __restrict__ out) {
    __shared__ float cs[TLEN];                       // c_i = 2^{-ds'[i]}

    const int q = threadIdx.x;                       // lane
    const int b = blockIdx.x;

    // ---- prologue: 16 costs per thread --------------------------------------
    const float L2E = 1.4426950408889634f;
    float mysum = 0.0f;
    #pragma unroll
    for (int i = 0; i < 4; ++i) {
        float4 xv = ((const float4*)(x + b * TLEN))[4 * q + i];
        float4 yv = ((const float4*)(y + b * TLEN))[4 * q + i];
        float f0 = (xv.x - yv.x) * (xv.x - yv.x) * L2E;
        float f1 = (xv.y - yv.y) * (xv.y - yv.y) * L2E;
        float f2 = (xv.z - yv.z) * (xv.z - yv.z) * L2E;
        float f3 = (xv.w - yv.w) * (xv.w - yv.w) * L2E;
        cs[16 * q + 4 * i + 0] = exp2f(-f0);
        cs[16 * q + 4 * i + 1] = exp2f(-f1);
        cs[16 * q + 4 * i + 2] = exp2f(-f2);
        cs[16 * q + 4 * i + 3] = exp2f(-f3);
        mysum += (f0 + f1) + (f2 + f3);
    }
    #pragma unroll
    for (int o = 16; o; o >>= 1) mysum += __shfl_xor_sync(0xffffffffu, mysum, o);
    const float P = mysum;                           // all lanes agree
    __syncwarp();

    // ---- state --------------------------------------------------------------
    float u[CPL];                                    // col carries, RAW, frame k
    #pragma unroll
    for (int j = 0; j < CPL; ++j) u[j] = 0.0f;
    float nb[ROWS];                                  // boundary (col 16q+15), frame k
    #pragma unroll
    for (int r = 0; r < ROWS; ++r) nb[r] = 0.0f;
    float dg = (q == 0) ? 1.0f : 0.0f;               // diag input (<= 2), frame k
    int   k = 0, eu = -127;

    for (int ts = 0; ts < WSUP; ++ts) {
        // ---- handoff: pure shfl (no seam!) ----
        float l[ROWS];
        #pragma unroll
        for (int r = 0; r < ROWS; ++r) l[r] = __shfl_up_sync(0xffffffffu, nb[r], 1);
        int kp = __shfl_up_sync(0xffffffffu, k, 1);
        const bool z = (q == 0);
        #pragma unroll
        for (int r = 0; r < ROWS; ++r) l[r] = z ? 0.0f : l[r];   // column-0 boundary
        kp = z ? k : kp;

        // ---- joint pre-tile renorm: all tile inputs -> <= 2 ----
        const int dk = kp - k;
        const float mlx = fmaxf(fmaxf(fmaxf(l[0], l[1]), fmaxf(l[2], l[3])),
                                fmaxf(fmaxf(l[4], l[5]), fmaxf(l[6], l[7])));
        const int el = ((__float_as_int(mlx) >> 23) - 127) + dk;
        int s = el > eu ? el : eu;
        s = s > 0 ? s : 0;
        const int kt = k + s;                        // tile frame
        int hl = dk - s;
        hl = hl > 126 ? 126 : hl;
        const float fa = (hl < -126) ? 0.0f : __int_as_float((hl + 127) << 23);
        const float uf = (s > 126) ? 0.0f : __int_as_float((127 - s) << 23);
        #pragma unroll
        for (int r = 0; r < ROWS; ++r) l[r] *= fa;

        // ---- row costs (chain-independent address) ----
        int ridx = ts - q;
        ridx = ridx < 0 ? 0 : (ridx > RB - 1 ? RB - 1 : ridx);
        const float4 ca = *(const float4*)&cs[ROWS * ridx];
        const float4 cb = *(const float4*)&cs[ROWS * ridx + 4];
        float c8[ROWS];
        c8[0] = ca.x; c8[1] = ca.y; c8[2] = ca.z; c8[3] = ca.w;
        c8[4] = cb.x; c8[5] = cb.y; c8[6] = cb.z; c8[7] = cb.w;

        // ---- row 0 (uf folded): p_j = c0*p_{j-1} + (u_j + u_{j-1})*uf ----
        float p[CPL];
        {
            float a[CPL];
            a[0] = (u[0] + dg) * uf;
            #pragma unroll
            for (int j = 1; j < CPL; ++j) a[j] = (u[j] + u[j - 1]) * uf;
            p[0] = fmaf(c8[0], l[0], a[0]);
            #pragma unroll
            for (int j = 1; j < CPL; ++j) p[j] = fmaf(c8[0], p[j - 1], a[j]);
        }
        nb[0] = p[CPL - 1];
        float dl = l[0];

        // ---- rows 1..7: p_j = c_r*p_{j-1} + (p_j + p_{j-1}) ----
        #pragma unroll
        for (int r = 1; r < ROWS; ++r) {
            float a[CPL];
            a[0] = p[0] + dl;
            #pragma unroll
            for (int j = 1; j < CPL; ++j) a[j] = p[j] + p[j - 1];
            p[0] = fmaf(c8[r], l[r], a[0]);
            #pragma unroll
            for (int j = 1; j < CPL; ++j) p[j] = fmaf(c8[r], p[j - 1], a[j]);
            nb[r] = p[CPL - 1];
            dl = l[r];
        }

        // ---- tail: commit raw, next-slot eu (alu, off-path) ----
        #pragma unroll
        for (int j = 0; j < CPL; ++j) u[j] = p[j];
        dg = dl;                                     // = scaled l[7], frame kt
        k = kt;
        float mxu = u[0];
        #pragma unroll
        for (int j = 1; j < CPL; ++j) mxu = fmaxf(mxu, u[j]);
        eu = (__float_as_int(mxu) >> 23) - 127;
    }

    if (q == 31) {
        // R(T,T)*log2e = P - k - log2(W_raw); unscale by ln2; mean over batches.
        float Rl2 = P - (float)k - __log2f(u[CPL - 1]);
        atomicAdd(out, Rl2 * 0.6931471805599453f * (1.0f / BATCH));
    }
}

extern "C" void kernel_launch(void* const* d_in, const int* in_sizes, int n_in,
                              void* d_out, int out_size) {
    const float* x = (const float*)d_in[0];
    const float* y = (const float*)d_in[1];
    cudaMemsetAsync(d_out, 0, sizeof(float));
    softdtw_kernel<<<BATCH, NTH>>>(x, y, (float*)d_out);
}